// round 14
// baseline (speedup 1.0000x reference)
#include <cuda_runtime.h>
#include <cuda_fp16.h>
#include <cstdint>
#include <math.h>

// ================= problem constants =================
#define B_ROWS 2048
#define KDIM   768
#define NLEV   6

// padded class rows (multiples of 128):
// bases 0,128,256,512,1408,4480 ; total 16512 ; tiles 1,1,2,7,24,94 = 129
#define BROWS_TOT 16512
#define NTILES    129
#define MTILES    16
#define NKS       12     // 768 / 64

#define NPAR_TOT 4140

// ================= device scratch =================
__device__ __align__(1024) __half g_A[(size_t)B_ROWS * KDIM];     // x fp16
__device__ __align__(1024) __half g_B[(size_t)BROWS_TOT * KDIM];  // W fp16
__device__ int2 g_bounds[NPAR_TOT];   // (start, len) packed

// ================= helpers =================
__device__ __forceinline__ uint32_t smem_u32(const void* p) {
    uint32_t r;
    asm("{ .reg .u64 t; cvta.to.shared.u64 t, %1; cvt.u32.u64 %0, t; }"
        : "=r"(r) : "l"(p));
    return r;
}
__device__ __forceinline__ void cp_async16(uint32_t s, const void* g) {
    asm volatile("cp.async.cg.shared.global [%0], [%1], 16;" :: "r"(s), "l"(g));
}
__device__ __forceinline__ void cp_async_commit() {
    asm volatile("cp.async.commit_group;" ::: "memory");
}
__device__ __forceinline__ void cp_async_wait1() {
    asm volatile("cp.async.wait_group 1;" ::: "memory");
}
__device__ __forceinline__ void ldsm_x4(uint32_t* r, uint32_t addr) {
    asm volatile("ldmatrix.sync.aligned.m8n8.x4.shared.b16 {%0,%1,%2,%3}, [%4];"
        : "=r"(r[0]), "=r"(r[1]), "=r"(r[2]), "=r"(r[3]) : "r"(addr));
}
__device__ __forceinline__ void mma16816(float* d, const uint32_t* a,
                                          uint32_t b0, uint32_t b1) {
    asm volatile(
        "mma.sync.aligned.m16n8k16.row.col.f32.f16.f16.f32 "
        "{%0,%1,%2,%3}, {%4,%5,%6,%7}, {%8,%9}, {%0,%1,%2,%3};"
        : "+f"(d[0]), "+f"(d[1]), "+f"(d[2]), "+f"(d[3])
        : "r"(a[0]), "r"(a[1]), "r"(a[2]), "r"(a[3]), "r"(b0), "r"(b1));
}

// ================= fused prep: conv_x + conv_w + bounds ====================
#define PREP_X_BLOCKS 1536          /* B_ROWS*KDIM/4 / 256 */
#define PREP_W_BLOCKS 12384         /* BROWS_TOT*KDIM/4 / 256 */
#define PREP_B_BLOCKS 17
#define PREP_BLOCKS   (PREP_X_BLOCKS + PREP_W_BLOCKS + PREP_B_BLOCKS)

__global__ void prep_kernel(const float* __restrict__ x,
                            const float* __restrict__ W0, const float* __restrict__ W1,
                            const float* __restrict__ W2, const float* __restrict__ W3,
                            const float* __restrict__ W4, const float* __restrict__ W5,
                            const int* __restrict__ p1, const int* __restrict__ p2,
                            const int* __restrict__ p3, const int* __restrict__ p4,
                            const int* __restrict__ p5)
{
    const int bid = blockIdx.x;
    if (bid < PREP_X_BLOCKS) {
        int idx = bid * 256 + threadIdx.x;
        int j = idx * 4;
        float4 v = *reinterpret_cast<const float4*>(x + j);
        float vv[4] = {v.x, v.y, v.z, v.w};
        __align__(8) __half h[4];
#pragma unroll
        for (int i = 0; i < 4; i++) h[i] = __float2half_rn(vv[i]);
        *reinterpret_cast<uint64_t*>(&g_A[j]) = *reinterpret_cast<uint64_t*>(h);
        return;
    }
    if (bid < PREP_X_BLOCKS + PREP_W_BLOCKS) {
        int idx = (bid - PREP_X_BLOCKS) * 256 + threadIdx.x;
        int r = idx / (KDIM / 4);
        int j = (idx % (KDIM / 4)) * 4;

        int lvl, base;
        if      (r < 128)  { lvl = 0; base = 0; }
        else if (r < 256)  { lvl = 1; base = 128; }
        else if (r < 512)  { lvl = 2; base = 256; }
        else if (r < 1408) { lvl = 3; base = 512; }
        else if (r < 4480) { lvl = 4; base = 1408; }
        else               { lvl = 5; base = 4480; }
        const int Cs[NLEV] = {20, 70, 250, 800, 3000, 12000};
        const float* Ws[NLEV] = {W0, W1, W2, W3, W4, W5};
        int local = r - base;

        float vv[4] = {0.f, 0.f, 0.f, 0.f};
        if (local < Cs[lvl]) {
            float4 v = *reinterpret_cast<const float4*>(Ws[lvl] + (size_t)local * KDIM + j);
            vv[0] = v.x; vv[1] = v.y; vv[2] = v.z; vv[3] = v.w;
        }
        __align__(8) __half h[4];
#pragma unroll
        for (int i = 0; i < 4; i++) h[i] = __float2half_rn(vv[i]);
        *reinterpret_cast<uint64_t*>(&g_B[(size_t)r * KDIM + j]) = *reinterpret_cast<uint64_t*>(h);
        return;
    }
    // bounds part -> packed (start, len)
    int i = (bid - PREP_X_BLOCKS - PREP_W_BLOCKS) * 256 + threadIdx.x;
    if (i >= NPAR_TOT) return;
    int lvl, off;
    if      (i < 20)   { lvl = 0; off = 0; }
    else if (i < 90)   { lvl = 1; off = 20; }
    else if (i < 340)  { lvl = 2; off = 90; }
    else if (i < 1140) { lvl = 3; off = 340; }
    else               { lvl = 4; off = 1140; }
    const int Cc[5] = {70, 250, 800, 3000, 12000};
    const int* pars[5] = {p1, p2, p3, p4, p5};
    const int* a = pars[lvl];
    int n = Cc[lvl];
    int pid = i - off;

    int lo = 0, hi = n;
    while (lo < hi) { int mid = (lo + hi) >> 1; if (a[mid] < pid) lo = mid + 1; else hi = mid; }
    int start = lo;
    hi = n;
    while (lo < hi) { int mid = (lo + hi) >> 1; if (a[mid] <= pid) lo = mid + 1; else hi = mid; }
    g_bounds[i] = make_int2(start, lo - start);
}

// ================= HMMA GEMM: K=64 slabs, 12 iters, 3 stages ==============
#define B_OFF       16384
#define STAGE_BYTES 32768
#define NSTAGE      3
#define SMEM_TOTAL  (NSTAGE * STAGE_BYTES)   /* 98304 */

__global__ void __launch_bounds__(128, 2)
tree_gemm_kernel(float* __restrict__ out,
                 const float* __restrict__ bb0, const float* __restrict__ bb1,
                 const float* __restrict__ bb2, const float* __restrict__ bb3,
                 const float* __restrict__ bb4, const float* __restrict__ bb5)
{
    extern __shared__ char smem[];
    const uint32_t sb = smem_u32(smem);
    const int tid  = threadIdx.x;
    const int lane = tid & 31;
    const int warp = tid >> 5;
    const int wm   = warp & 1;
    const int wn   = warp >> 1;

    const int bx = blockIdx.x;
    int lvl;
    if      (bx < 1)  lvl = 0;
    else if (bx < 2)  lvl = 1;
    else if (bx < 4)  lvl = 2;
    else if (bx < 11) lvl = 3;
    else if (bx < 35) lvl = 4;
    else              lvl = 5;
    const int    tstart[NLEV]  = {0, 1, 2, 4, 11, 35};
    const int    padbase[NLEV] = {0, 128, 256, 512, 1408, 4480};
    const int    Cs[NLEV]      = {20, 70, 250, 800, 3000, 12000};
    const size_t obase[NLEV]   = {0, (size_t)B_ROWS*20, (size_t)B_ROWS*90, (size_t)B_ROWS*340,
                                  (size_t)B_ROWS*1140, (size_t)B_ROWS*4140};
    const float* biasArr[NLEV] = {bb0, bb1, bb2, bb3, bb4, bb5};

    const int   n0l   = (bx - tstart[lvl]) * 128;
    const int   brow0 = padbase[lvl] + n0l;
    const int   C     = Cs[lvl];
    const size_t ob   = obase[lvl];
    const float* bias = biasArr[lvl];
    const int   m0    = blockIdx.y * 128;

    auto load_slab = [&](int ks, int st) {
        const int kofs = ks * 64;
        uint32_t base = sb + st * STAGE_BYTES;
#pragma unroll
        for (int i = 0; i < 8; i++) {
            int cid = tid + i * 128;
            int row = cid >> 3, c = cid & 7;
            uint32_t sw = row * 128 + ((c ^ (row & 7)) << 4);
            cp_async16(base + sw,
                       &g_A[(size_t)(m0 + row) * KDIM + kofs + c * 8]);
            cp_async16(base + B_OFF + sw,
                       &g_B[(size_t)(brow0 + row) * KDIM + kofs + c * 8]);
        }
    };

    float acc[4][8][4];
#pragma unroll
    for (int i = 0; i < 4; i++)
#pragma unroll
        for (int j = 0; j < 8; j++)
#pragma unroll
            for (int k = 0; k < 4; k++) acc[i][j][k] = 0.f;

    load_slab(0, 0); cp_async_commit();
    load_slab(1, 1); cp_async_commit();

    int st = 0;
    for (int ks = 0; ks < NKS; ks++) {
        cp_async_wait1();
        __syncthreads();

        if (ks + 2 < NKS) load_slab(ks + 2, (ks + 2) % NSTAGE);
        cp_async_commit();

        uint32_t base = sb + st * STAGE_BYTES;
#pragma unroll
        for (int kk = 0; kk < 4; kk++) {
            uint32_t bfr[4][4];
#pragma unroll
            for (int nj4 = 0; nj4 < 4; nj4++) {
                int row = wn * 64 + nj4 * 16 + (lane & 7) + ((lane & 16) ? 8 : 0);
                int c   = kk * 2 + ((lane >> 3) & 1);
                ldsm_x4(bfr[nj4], base + B_OFF + row * 128 + ((c ^ (row & 7)) << 4));
            }
            uint32_t afr[4][4];
#pragma unroll
            for (int mi = 0; mi < 4; mi++) {
                int row = wm * 64 + mi * 16 + (lane & 15);
                int c   = kk * 2 + (lane >> 4);
                ldsm_x4(afr[mi], base + row * 128 + ((c ^ (row & 7)) << 4));
            }
#pragma unroll
            for (int mi = 0; mi < 4; mi++)
#pragma unroll
                for (int nj = 0; nj < 8; nj++)
                    mma16816(acc[mi][nj], afr[mi],
                             bfr[nj >> 1][(nj & 1) * 2], bfr[nj >> 1][(nj & 1) * 2 + 1]);
        }
        st++; if (st == NSTAGE) st = 0;
    }

    // ---- epilogue: write exp(logit + bias) ----
    const int ncol0 = n0l + wn * 64;
    if (ncol0 + 64 <= C) {
#pragma unroll
        for (int mi = 0; mi < 4; mi++) {
            int r0 = m0 + wm * 64 + mi * 16 + (lane >> 2);
#pragma unroll
            for (int nj = 0; nj < 8; nj++) {
                int n = ncol0 + nj * 8 + (lane & 3) * 2;
                float2 bv = *reinterpret_cast<const float2*>(bias + n);
                float2 v0 = make_float2(__expf(acc[mi][nj][0] + bv.x),
                                        __expf(acc[mi][nj][1] + bv.y));
                float2 v1 = make_float2(__expf(acc[mi][nj][2] + bv.x),
                                        __expf(acc[mi][nj][3] + bv.y));
                *reinterpret_cast<float2*>(out + ob + (size_t)r0 * C + n)       = v0;
                *reinterpret_cast<float2*>(out + ob + (size_t)(r0 + 8) * C + n) = v1;
            }
        }
    } else {
#pragma unroll
        for (int mi = 0; mi < 4; mi++) {
            int r0 = m0 + wm * 64 + mi * 16 + (lane >> 2);
#pragma unroll
            for (int nj = 0; nj < 8; nj++) {
                int n = ncol0 + nj * 8 + (lane & 3) * 2;
                if (n < C) {
                    out[ob + (size_t)r0 * C + n]       = __expf(acc[mi][nj][0] + bias[n]);
                    out[ob + (size_t)(r0 + 8) * C + n] = __expf(acc[mi][nj][2] + bias[n]);
                }
                if (n + 1 < C) {
                    out[ob + (size_t)r0 * C + n + 1]       = __expf(acc[mi][nj][1] + bias[n + 1]);
                    out[ob + (size_t)(r0 + 8) * C + n + 1] = __expf(acc[mi][nj][3] + bias[n + 1]);
                }
            }
        }
    }
}

// ================= fused small levels: root + L1 + L2 + L3 =================
__global__ void __launch_bounds__(256)
chain_small_kernel(float* __restrict__ out)
{
    __shared__ float sA[800];
    __shared__ float sB[800];
    __shared__ float sred;

    const int b   = blockIdx.x;
    const int tid = threadIdx.x;

    float* row0 = out + (size_t)b * 20;
    float e = 0.f;
    if (tid < 20) e = row0[tid];
    if (tid < 32) {
        float v = e;
#pragma unroll
        for (int o = 16; o > 0; o >>= 1)
            v += __shfl_down_sync(0xffffffffu, v, o);
        if (tid == 0) sred = v;
    }
    __syncthreads();
    if (tid < 20) {
        float p = __fdividef(e, sred);
        row0[tid] = p;
        sA[tid]   = p;
    }
    __syncthreads();

    const int    Ps[3]  = {20, 70, 250};
    const int    Cs[3]  = {70, 250, 800};
    const int    Bo[3]  = {0, 20, 90};
    const size_t obs[3] = {(size_t)B_ROWS*20, (size_t)B_ROWS*90, (size_t)B_ROWS*340};

    float* prev = sA;
    float* cur  = sB;
#pragma unroll
    for (int l = 0; l < 3; l++) {
        const int P = Ps[l], C = Cs[l], bo = Bo[l];
        float* rowL = out + obs[l] + (size_t)b * C;
        if (tid < P) {
            int2 be = __ldg(&g_bounds[bo + tid]);
            int s0 = be.x, len = be.y;
            if (len > 0) {
                float s = 0.f;
                for (int c = s0; c < s0 + len; c++) s += __ldg(rowL + c);
                float scale = __fdividef(prev[tid], s);
                for (int c = s0; c < s0 + len; c++) {
                    float v = rowL[c] * scale;
                    rowL[c] = v;
                    cur[c]  = v;
                }
            }
        }
        __syncthreads();
        float* t = prev; prev = cur; cur = t;
    }
}

// ================= seg softmax for big levels (values pre-exp'd) ==========
__global__ void __launch_bounds__(256)
seg_softmax_kernel(float* __restrict__ outL, const float* __restrict__ outP,
                   int boff, int C, int P) {
    int idx = blockIdx.x * blockDim.x + threadIdx.x;
    if (idx >= B_ROWS * P) return;
    int b = idx / P;
    int pid = idx - b * P;
    int2 be = __ldg(&g_bounds[boff + pid]);
    int start = be.x, len = be.y;
    if (len <= 0) return;

    float* row = outL + (size_t)b * C + start;
    float pp = __ldg(outP + (size_t)b * P + pid);

    if (len <= 8) {
        // register-cached, two partial sum chains for ILP
        float ebuf[8];
        float s0 = 0.f, s1 = 0.f;
#pragma unroll
        for (int i = 0; i < 8; i += 2) {
            float v0 = (i     < len) ? __ldg(row + i)     : 0.f;
            float v1 = (i + 1 < len) ? __ldg(row + i + 1) : 0.f;
            ebuf[i]     = v0;
            ebuf[i + 1] = v1;
            s0 += v0;
            s1 += v1;
        }
        float scale = __fdividef(pp, s0 + s1);
#pragma unroll
        for (int i = 0; i < 8; i++)
            if (i < len) row[i] = ebuf[i] * scale;
    } else {
        float s = 0.f;
        for (int c = 0; c < len; c++) s += __ldg(row + c);
        float scale = __fdividef(pp, s);
        for (int c = 0; c < len; c++) row[c] = row[c] * scale;
    }
}

// ================= launch =================
extern "C" void kernel_launch(void* const* d_in, const int* in_sizes, int n_in,
                              void* d_out, int out_size)
{
    const float* x = (const float*)d_in[0];
    const float* W[NLEV];
    const float* bias[NLEV];
    for (int i = 0; i < NLEV; i++) {
        W[i]    = (const float*)d_in[1 + 2 * i];
        bias[i] = (const float*)d_in[2 + 2 * i];
    }
    const int* par[5];
    for (int l = 0; l < 5; l++) par[l] = (const int*)d_in[13 + l];
    float* out = (float*)d_out;

    cudaFuncSetAttribute(tree_gemm_kernel,
                         cudaFuncAttributeMaxDynamicSharedMemorySize, SMEM_TOTAL);

    // 1) fused prep: conv_x + conv_w + bounds
    prep_kernel<<<PREP_BLOCKS, 256>>>(x, W[0], W[1], W[2], W[3], W[4], W[5],
                                      par[0], par[1], par[2], par[3], par[4]);

    // 2) fused HMMA GEMM, writes exp(logit)
    dim3 grid(NTILES, MTILES);
    tree_gemm_kernel<<<grid, 128, SMEM_TOTAL>>>(out, bias[0], bias[1], bias[2],
                                                bias[3], bias[4], bias[5]);

    // 3) root + levels 1-3 fused (one block per row)
    chain_small_kernel<<<B_ROWS, 256>>>(out);

    // 4) level 4 (profiled slot)
    {
        int nthreads = B_ROWS * 800;
        seg_softmax_kernel<<<(nthreads + 255) / 256, 256>>>(
            out + (size_t)B_ROWS * 1140, out + (size_t)B_ROWS * 340, 340, 3000, 800);
    }
    // 5) level 5
    {
        int nthreads = B_ROWS * 3000;
        seg_softmax_kernel<<<(nthreads + 255) / 256, 256>>>(
            out + (size_t)B_ROWS * 4140, out + (size_t)B_ROWS * 1140, 1140, 12000, 3000);
    }
}

// round 15
// speedup vs baseline: 1.0199x; 1.0199x over previous
#include <cuda_runtime.h>
#include <cuda_fp16.h>
#include <cstdint>
#include <math.h>

// ================= problem constants =================
#define B_ROWS 2048
#define KDIM   768
#define NLEV   6

// padded class rows: bases 0,128,256,512,1408,4480 ; total 16512 ; 129 tiles
#define BROWS_TOT 16512
#define NTILES    129
#define MTILES    16
#define NKS       12     // 768 / 64

#define NPAR_TOT 4140

// ================= device scratch =================
__device__ __align__(1024) __half g_A[(size_t)B_ROWS * KDIM];     // x fp16
__device__ __align__(1024) __half g_B[(size_t)BROWS_TOT * KDIM];  // W fp16
__device__ int g_gs[NPAR_TOT];
__device__ int g_ge[NPAR_TOT];

// ================= helpers =================
__device__ __forceinline__ uint32_t smem_u32(const void* p) {
    uint32_t r;
    asm("{ .reg .u64 t; cvta.to.shared.u64 t, %1; cvt.u32.u64 %0, t; }"
        : "=r"(r) : "l"(p));
    return r;
}
__device__ __forceinline__ void cp_async16(uint32_t s, const void* g) {
    asm volatile("cp.async.cg.shared.global [%0], [%1], 16;" :: "r"(s), "l"(g));
}
__device__ __forceinline__ void cp_async_commit() {
    asm volatile("cp.async.commit_group;" ::: "memory");
}
__device__ __forceinline__ void cp_async_wait1() {
    asm volatile("cp.async.wait_group 1;" ::: "memory");
}
__device__ __forceinline__ void ldsm_x4(uint32_t* r, uint32_t addr) {
    asm volatile("ldmatrix.sync.aligned.m8n8.x4.shared.b16 {%0,%1,%2,%3}, [%4];"
        : "=r"(r[0]), "=r"(r[1]), "=r"(r[2]), "=r"(r[3]) : "r"(addr));
}
__device__ __forceinline__ void mma16816(float* d, const uint32_t* a,
                                          uint32_t b0, uint32_t b1) {
    asm volatile(
        "mma.sync.aligned.m16n8k16.row.col.f32.f16.f16.f32 "
        "{%0,%1,%2,%3}, {%4,%5,%6,%7}, {%8,%9}, {%0,%1,%2,%3};"
        : "+f"(d[0]), "+f"(d[1]), "+f"(d[2]), "+f"(d[3])
        : "r"(a[0]), "r"(a[1]), "r"(a[2]), "r"(a[3]), "r"(b0), "r"(b1));
}

// ================= fused prep: conv_x + conv_w + bounds ====================
#define PREP_X_BLOCKS 1536
#define PREP_W_BLOCKS 12384
#define PREP_B_BLOCKS 17
#define PREP_BLOCKS   (PREP_X_BLOCKS + PREP_W_BLOCKS + PREP_B_BLOCKS)

__global__ void prep_kernel(const float* __restrict__ x,
                            const float* __restrict__ W0, const float* __restrict__ W1,
                            const float* __restrict__ W2, const float* __restrict__ W3,
                            const float* __restrict__ W4, const float* __restrict__ W5,
                            const int* __restrict__ p1, const int* __restrict__ p2,
                            const int* __restrict__ p3, const int* __restrict__ p4,
                            const int* __restrict__ p5)
{
    const int bid = blockIdx.x;
    if (bid < PREP_X_BLOCKS) {
        int idx = bid * 256 + threadIdx.x;
        int j = idx * 4;
        float4 v = *reinterpret_cast<const float4*>(x + j);
        float vv[4] = {v.x, v.y, v.z, v.w};
        __align__(8) __half h[4];
#pragma unroll
        for (int i = 0; i < 4; i++) h[i] = __float2half_rn(vv[i]);
        *reinterpret_cast<uint64_t*>(&g_A[j]) = *reinterpret_cast<uint64_t*>(h);
        return;
    }
    if (bid < PREP_X_BLOCKS + PREP_W_BLOCKS) {
        int idx = (bid - PREP_X_BLOCKS) * 256 + threadIdx.x;
        int r = idx / (KDIM / 4);
        int j = (idx % (KDIM / 4)) * 4;

        int lvl, base;
        if      (r < 128)  { lvl = 0; base = 0; }
        else if (r < 256)  { lvl = 1; base = 128; }
        else if (r < 512)  { lvl = 2; base = 256; }
        else if (r < 1408) { lvl = 3; base = 512; }
        else if (r < 4480) { lvl = 4; base = 1408; }
        else               { lvl = 5; base = 4480; }
        const int Cs[NLEV] = {20, 70, 250, 800, 3000, 12000};
        const float* Ws[NLEV] = {W0, W1, W2, W3, W4, W5};
        int local = r - base;

        float vv[4] = {0.f, 0.f, 0.f, 0.f};
        if (local < Cs[lvl]) {
            float4 v = *reinterpret_cast<const float4*>(Ws[lvl] + (size_t)local * KDIM + j);
            vv[0] = v.x; vv[1] = v.y; vv[2] = v.z; vv[3] = v.w;
        }
        __align__(8) __half h[4];
#pragma unroll
        for (int i = 0; i < 4; i++) h[i] = __float2half_rn(vv[i]);
        *reinterpret_cast<uint64_t*>(&g_B[(size_t)r * KDIM + j]) = *reinterpret_cast<uint64_t*>(h);
        return;
    }
    int i = (bid - PREP_X_BLOCKS - PREP_W_BLOCKS) * 256 + threadIdx.x;
    if (i >= NPAR_TOT) return;
    int lvl, off;
    if      (i < 20)   { lvl = 0; off = 0; }
    else if (i < 90)   { lvl = 1; off = 20; }
    else if (i < 340)  { lvl = 2; off = 90; }
    else if (i < 1140) { lvl = 3; off = 340; }
    else               { lvl = 4; off = 1140; }
    const int Cc[5] = {70, 250, 800, 3000, 12000};
    const int* pars[5] = {p1, p2, p3, p4, p5};
    const int* a = pars[lvl];
    int n = Cc[lvl];
    int pid = i - off;

    int lo = 0, hi = n;
    while (lo < hi) { int mid = (lo + hi) >> 1; if (a[mid] < pid) lo = mid + 1; else hi = mid; }
    int start = lo;
    hi = n;
    while (lo < hi) { int mid = (lo + hi) >> 1; if (a[mid] <= pid) lo = mid + 1; else hi = mid; }
    g_gs[i] = start;
    g_ge[i] = lo;
}

// ================= HMMA GEMM: 256 thr (8 warps 4m x 2n, 32x64 tiles),
// K=64 slabs, 12 iters, 3 stages =================
#define B_OFF       16384
#define STAGE_BYTES 32768
#define NSTAGE      3
#define SMEM_TOTAL  (NSTAGE * STAGE_BYTES)   /* 98304 */

__global__ void __launch_bounds__(256, 2)
tree_gemm_kernel(float* __restrict__ out,
                 const float* __restrict__ bb0, const float* __restrict__ bb1,
                 const float* __restrict__ bb2, const float* __restrict__ bb3,
                 const float* __restrict__ bb4, const float* __restrict__ bb5)
{
    extern __shared__ char smem[];
    const uint32_t sb = smem_u32(smem);
    const int tid  = threadIdx.x;
    const int lane = tid & 31;
    const int warp = tid >> 5;
    const int wm   = warp & 3;    // m offset 32*wm
    const int wn   = warp >> 2;   // n offset 64*wn

    const int bx = blockIdx.x;
    int lvl;
    if      (bx < 1)  lvl = 0;
    else if (bx < 2)  lvl = 1;
    else if (bx < 4)  lvl = 2;
    else if (bx < 11) lvl = 3;
    else if (bx < 35) lvl = 4;
    else              lvl = 5;
    const int    tstart[NLEV]  = {0, 1, 2, 4, 11, 35};
    const int    padbase[NLEV] = {0, 128, 256, 512, 1408, 4480};
    const int    Cs[NLEV]      = {20, 70, 250, 800, 3000, 12000};
    const size_t obase[NLEV]   = {0, (size_t)B_ROWS*20, (size_t)B_ROWS*90, (size_t)B_ROWS*340,
                                  (size_t)B_ROWS*1140, (size_t)B_ROWS*4140};
    const float* biasArr[NLEV] = {bb0, bb1, bb2, bb3, bb4, bb5};

    const int   n0l   = (bx - tstart[lvl]) * 128;
    const int   brow0 = padbase[lvl] + n0l;
    const int   C     = Cs[lvl];
    const size_t ob   = obase[lvl];
    const float* bias = biasArr[lvl];
    const int   m0    = blockIdx.y * 128;

    // K64 slab loader: A(16KB)+B(16KB), 128B rows, swizzle c ^ (row&7);
    // 256 threads x 8 chunks
    auto load_slab = [&](int ks, int st) {
        const int kofs = ks * 64;
        uint32_t base = sb + st * STAGE_BYTES;
#pragma unroll
        for (int i = 0; i < 4; i++) {
            int cid = tid + i * 256;
            int row = cid >> 3, c = cid & 7;
            uint32_t sw = row * 128 + ((c ^ (row & 7)) << 4);
            cp_async16(base + sw,
                       &g_A[(size_t)(m0 + row) * KDIM + kofs + c * 8]);
            cp_async16(base + B_OFF + sw,
                       &g_B[(size_t)(brow0 + row) * KDIM + kofs + c * 8]);
        }
    };

    float acc[2][8][4];
#pragma unroll
    for (int i = 0; i < 2; i++)
#pragma unroll
        for (int j = 0; j < 8; j++)
#pragma unroll
            for (int k = 0; k < 4; k++) acc[i][j][k] = 0.f;

    load_slab(0, 0); cp_async_commit();
    load_slab(1, 1); cp_async_commit();

    int st = 0;
    for (int ks = 0; ks < NKS; ks++) {
        cp_async_wait1();
        __syncthreads();

        if (ks + 2 < NKS) load_slab(ks + 2, (ks + 2) % NSTAGE);
        cp_async_commit();

        uint32_t base = sb + st * STAGE_BYTES;
#pragma unroll
        for (int kk = 0; kk < 4; kk++) {
            uint32_t bfr[4][4];
#pragma unroll
            for (int nj4 = 0; nj4 < 4; nj4++) {
                int row = wn * 64 + nj4 * 16 + (lane & 7) + ((lane & 16) ? 8 : 0);
                int c   = kk * 2 + ((lane >> 3) & 1);
                ldsm_x4(bfr[nj4], base + B_OFF + row * 128 + ((c ^ (row & 7)) << 4));
            }
            uint32_t afr[2][4];
#pragma unroll
            for (int mi = 0; mi < 2; mi++) {
                int row = wm * 32 + mi * 16 + (lane & 15);
                int c   = kk * 2 + (lane >> 4);
                ldsm_x4(afr[mi], base + row * 128 + ((c ^ (row & 7)) << 4));
            }
#pragma unroll
            for (int mi = 0; mi < 2; mi++)
#pragma unroll
                for (int nj = 0; nj < 8; nj++)
                    mma16816(acc[mi][nj], afr[mi],
                             bfr[nj >> 1][(nj & 1) * 2], bfr[nj >> 1][(nj & 1) * 2 + 1]);
        }
        st++; if (st == NSTAGE) st = 0;
    }

    // ---- epilogue: write exp(logit + bias) ----
    const int ncol0 = n0l + wn * 64;
    if (ncol0 + 64 <= C) {
#pragma unroll
        for (int mi = 0; mi < 2; mi++) {
            int r0 = m0 + wm * 32 + mi * 16 + (lane >> 2);
#pragma unroll
            for (int nj = 0; nj < 8; nj++) {
                int n = ncol0 + nj * 8 + (lane & 3) * 2;
                float2 bv = *reinterpret_cast<const float2*>(bias + n);
                float2 v0 = make_float2(__expf(acc[mi][nj][0] + bv.x),
                                        __expf(acc[mi][nj][1] + bv.y));
                float2 v1 = make_float2(__expf(acc[mi][nj][2] + bv.x),
                                        __expf(acc[mi][nj][3] + bv.y));
                *reinterpret_cast<float2*>(out + ob + (size_t)r0 * C + n)       = v0;
                *reinterpret_cast<float2*>(out + ob + (size_t)(r0 + 8) * C + n) = v1;
            }
        }
    } else {
#pragma unroll
        for (int mi = 0; mi < 2; mi++) {
            int r0 = m0 + wm * 32 + mi * 16 + (lane >> 2);
#pragma unroll
            for (int nj = 0; nj < 8; nj++) {
                int n = ncol0 + nj * 8 + (lane & 3) * 2;
                if (n < C) {
                    out[ob + (size_t)r0 * C + n]       = __expf(acc[mi][nj][0] + bias[n]);
                    out[ob + (size_t)(r0 + 8) * C + n] = __expf(acc[mi][nj][2] + bias[n]);
                }
                if (n + 1 < C) {
                    out[ob + (size_t)r0 * C + n + 1]       = __expf(acc[mi][nj][1] + bias[n + 1]);
                    out[ob + (size_t)(r0 + 8) * C + n + 1] = __expf(acc[mi][nj][3] + bias[n + 1]);
                }
            }
        }
    }
}

// ================= fused small levels: root + L1 + L2 + L3 (R13 form) =====
__global__ void __launch_bounds__(128)
chain_small_kernel(float* __restrict__ out)
{
    __shared__ float sA[800];
    __shared__ float sB[800];
    __shared__ float sred;

    const int b   = blockIdx.x;
    const int tid = threadIdx.x;

    float* row0 = out + (size_t)b * 20;
    float e = 0.f;
    if (tid < 20) e = row0[tid];
    if (tid < 32) {
        float v = e;
#pragma unroll
        for (int o = 16; o > 0; o >>= 1)
            v += __shfl_down_sync(0xffffffffu, v, o);
        if (tid == 0) sred = v;
    }
    __syncthreads();
    if (tid < 20) {
        float p = __fdividef(e, sred);
        row0[tid] = p;
        sA[tid]   = p;
    }
    __syncthreads();

    const int    Ps[3]  = {20, 70, 250};
    const int    Cs[3]  = {70, 250, 800};
    const int    Bo[3]  = {0, 20, 90};
    const size_t obs[3] = {(size_t)B_ROWS*20, (size_t)B_ROWS*90, (size_t)B_ROWS*340};

    float* prev = sA;
    float* cur  = sB;
#pragma unroll
    for (int l = 0; l < 3; l++) {
        const int P = Ps[l], C = Cs[l], bo = Bo[l];
        float* rowL = out + obs[l] + (size_t)b * C;
        for (int pid = tid; pid < P; pid += 128) {
            int s0 = __ldg(&g_gs[bo + pid]);
            int e0 = __ldg(&g_ge[bo + pid]);
            if (s0 >= e0) continue;
            float s = 0.f;
            for (int c = s0; c < e0; c++) s += __ldg(rowL + c);
            float scale = __fdividef(prev[pid], s);
            for (int c = s0; c < e0; c++) {
                float v = rowL[c] * scale;
                rowL[c] = v;
                cur[c]  = v;
            }
        }
        __syncthreads();
        float* t = prev; prev = cur; cur = t;
    }
}

// ================= seg softmax for big levels (R13 form) ===================
__global__ void seg_softmax_kernel(float* __restrict__ outL, const float* __restrict__ outP,
                                   int boff, int C, int P) {
    int idx = blockIdx.x * blockDim.x + threadIdx.x;
    if (idx >= B_ROWS * P) return;
    int b = idx / P;
    int pid = idx - b * P;
    int start = __ldg(&g_gs[boff + pid]);
    int end   = __ldg(&g_ge[boff + pid]);
    int len = end - start;
    if (len <= 0) return;

    float* row = outL + (size_t)b * C;
    float pp = __ldg(outP + (size_t)b * P + pid);

    if (len <= 8) {
        float ebuf[8];
        float s = 0.f;
#pragma unroll
        for (int i = 0; i < 8; i++) {
            float v = (i < len) ? __ldg(row + start + i) : 0.f;
            ebuf[i] = v;
            s += v;
        }
        float scale = __fdividef(pp, s);
#pragma unroll
        for (int i = 0; i < 8; i++)
            if (i < len) row[start + i] = ebuf[i] * scale;
    } else {
        float s = 0.f;
        for (int c = start; c < end; c++) s += __ldg(row + c);
        float scale = __fdividef(pp, s);
        for (int c = start; c < end; c++) row[c] = row[c] * scale;
    }
}

// ================= launch =================
extern "C" void kernel_launch(void* const* d_in, const int* in_sizes, int n_in,
                              void* d_out, int out_size)
{
    const float* x = (const float*)d_in[0];
    const float* W[NLEV];
    const float* bias[NLEV];
    for (int i = 0; i < NLEV; i++) {
        W[i]    = (const float*)d_in[1 + 2 * i];
        bias[i] = (const float*)d_in[2 + 2 * i];
    }
    const int* par[5];
    for (int l = 0; l < 5; l++) par[l] = (const int*)d_in[13 + l];
    float* out = (float*)d_out;

    cudaFuncSetAttribute(tree_gemm_kernel,
                         cudaFuncAttributeMaxDynamicSharedMemorySize, SMEM_TOTAL);

    // 1) fused prep: conv_x + conv_w + bounds
    prep_kernel<<<PREP_BLOCKS, 256>>>(x, W[0], W[1], W[2], W[3], W[4], W[5],
                                      par[0], par[1], par[2], par[3], par[4]);

    // 2) fused HMMA GEMM, writes exp(logit)
    dim3 grid(NTILES, MTILES);
    tree_gemm_kernel<<<grid, 256, SMEM_TOTAL>>>(out, bias[0], bias[1], bias[2],
                                                bias[3], bias[4], bias[5]);

    // 3) root + levels 1-3 fused (one block per row)
    chain_small_kernel<<<B_ROWS, 128>>>(out);

    // 4) level 4 (profiled slot)
    {
        int nthreads = B_ROWS * 800;
        seg_softmax_kernel<<<(nthreads + 255) / 256, 256>>>(
            out + (size_t)B_ROWS * 1140, out + (size_t)B_ROWS * 340, 340, 3000, 800);
    }
    // 5) level 5
    {
        int nthreads = B_ROWS * 3000;
        seg_softmax_kernel<<<(nthreads + 255) / 256, 256>>>(
            out + (size_t)B_ROWS * 4140, out + (size_t)B_ROWS * 1140, 1140, 12000, 3000);
    }
}

// round 16
// speedup vs baseline: 1.0453x; 1.0250x over previous
#include <cuda_runtime.h>
#include <cuda_fp16.h>
#include <cstdint>
#include <math.h>

// ================= problem constants =================
#define B_ROWS 2048
#define KDIM   768
#define NLEV   6

// padded class rows: bases 0,128,256,512,1408,4480 ; total 16512 ; 129 tiles
#define BROWS_TOT 16512
#define NTILES    129
#define MTILES    16
#define NKS       12     // 768 / 64

#define NPAR_TOT 4140

// ================= device scratch =================
__device__ __align__(1024) __half g_A[(size_t)B_ROWS * KDIM];     // x fp16
__device__ __align__(1024) __half g_B[(size_t)BROWS_TOT * KDIM];  // W fp16
__device__ int g_gs[NPAR_TOT];
__device__ int g_ge[NPAR_TOT];

// ================= helpers =================
__device__ __forceinline__ uint32_t smem_u32(const void* p) {
    uint32_t r;
    asm("{ .reg .u64 t; cvta.to.shared.u64 t, %1; cvt.u32.u64 %0, t; }"
        : "=r"(r) : "l"(p));
    return r;
}
__device__ __forceinline__ void cp_async16(uint32_t s, const void* g) {
    asm volatile("cp.async.cg.shared.global [%0], [%1], 16;" :: "r"(s), "l"(g));
}
__device__ __forceinline__ void cp_async_commit() {
    asm volatile("cp.async.commit_group;" ::: "memory");
}
__device__ __forceinline__ void cp_async_wait1() {
    asm volatile("cp.async.wait_group 1;" ::: "memory");
}
__device__ __forceinline__ void ldsm_x4(uint32_t* r, uint32_t addr) {
    asm volatile("ldmatrix.sync.aligned.m8n8.x4.shared.b16 {%0,%1,%2,%3}, [%4];"
        : "=r"(r[0]), "=r"(r[1]), "=r"(r[2]), "=r"(r[3]) : "r"(addr));
}
__device__ __forceinline__ void mma16816(float* d, const uint32_t* a,
                                          uint32_t b0, uint32_t b1) {
    asm volatile(
        "mma.sync.aligned.m16n8k16.row.col.f32.f16.f16.f32 "
        "{%0,%1,%2,%3}, {%4,%5,%6,%7}, {%8,%9}, {%0,%1,%2,%3};"
        : "+f"(d[0]), "+f"(d[1]), "+f"(d[2]), "+f"(d[3])
        : "r"(a[0]), "r"(a[1]), "r"(a[2]), "r"(a[3]), "r"(b0), "r"(b1));
}

// ================= fused prep: conv_x + conv_w + bounds ====================
#define PREP_X_BLOCKS 1536
#define PREP_W_BLOCKS 12384
#define PREP_B_BLOCKS 17
#define PREP_BLOCKS   (PREP_X_BLOCKS + PREP_W_BLOCKS + PREP_B_BLOCKS)

__global__ void prep_kernel(const float* __restrict__ x,
                            const float* __restrict__ W0, const float* __restrict__ W1,
                            const float* __restrict__ W2, const float* __restrict__ W3,
                            const float* __restrict__ W4, const float* __restrict__ W5,
                            const int* __restrict__ p1, const int* __restrict__ p2,
                            const int* __restrict__ p3, const int* __restrict__ p4,
                            const int* __restrict__ p5)
{
    const int bid = blockIdx.x;
    if (bid < PREP_X_BLOCKS) {
        int idx = bid * 256 + threadIdx.x;
        int j = idx * 4;
        float4 v = *reinterpret_cast<const float4*>(x + j);
        float vv[4] = {v.x, v.y, v.z, v.w};
        __align__(8) __half h[4];
#pragma unroll
        for (int i = 0; i < 4; i++) h[i] = __float2half_rn(vv[i]);
        *reinterpret_cast<uint64_t*>(&g_A[j]) = *reinterpret_cast<uint64_t*>(h);
        return;
    }
    if (bid < PREP_X_BLOCKS + PREP_W_BLOCKS) {
        int idx = (bid - PREP_X_BLOCKS) * 256 + threadIdx.x;
        int r = idx / (KDIM / 4);
        int j = (idx % (KDIM / 4)) * 4;

        int lvl, base;
        if      (r < 128)  { lvl = 0; base = 0; }
        else if (r < 256)  { lvl = 1; base = 128; }
        else if (r < 512)  { lvl = 2; base = 256; }
        else if (r < 1408) { lvl = 3; base = 512; }
        else if (r < 4480) { lvl = 4; base = 1408; }
        else               { lvl = 5; base = 4480; }
        const int Cs[NLEV] = {20, 70, 250, 800, 3000, 12000};
        const float* Ws[NLEV] = {W0, W1, W2, W3, W4, W5};
        int local = r - base;

        float vv[4] = {0.f, 0.f, 0.f, 0.f};
        if (local < Cs[lvl]) {
            float4 v = *reinterpret_cast<const float4*>(Ws[lvl] + (size_t)local * KDIM + j);
            vv[0] = v.x; vv[1] = v.y; vv[2] = v.z; vv[3] = v.w;
        }
        __align__(8) __half h[4];
#pragma unroll
        for (int i = 0; i < 4; i++) h[i] = __float2half_rn(vv[i]);
        *reinterpret_cast<uint64_t*>(&g_B[(size_t)r * KDIM + j]) = *reinterpret_cast<uint64_t*>(h);
        return;
    }
    int i = (bid - PREP_X_BLOCKS - PREP_W_BLOCKS) * 256 + threadIdx.x;
    if (i >= NPAR_TOT) return;
    int lvl, off;
    if      (i < 20)   { lvl = 0; off = 0; }
    else if (i < 90)   { lvl = 1; off = 20; }
    else if (i < 340)  { lvl = 2; off = 90; }
    else if (i < 1140) { lvl = 3; off = 340; }
    else               { lvl = 4; off = 1140; }
    const int Cc[5] = {70, 250, 800, 3000, 12000};
    const int* pars[5] = {p1, p2, p3, p4, p5};
    const int* a = pars[lvl];
    int n = Cc[lvl];
    int pid = i - off;

    int lo = 0, hi = n;
    while (lo < hi) { int mid = (lo + hi) >> 1; if (a[mid] < pid) lo = mid + 1; else hi = mid; }
    int start = lo;
    hi = n;
    while (lo < hi) { int mid = (lo + hi) >> 1; if (a[mid] <= pid) lo = mid + 1; else hi = mid; }
    g_gs[i] = start;
    g_ge[i] = lo;
}

// ================= HMMA GEMM: 4 warps (2m x 2n, 64x64 tiles), K=64 slabs,
// 12 iters, 3 stages, fragment double-buffering in kk loop =================
#define B_OFF       16384
#define STAGE_BYTES 32768
#define NSTAGE      3
#define SMEM_TOTAL  (NSTAGE * STAGE_BYTES)   /* 98304 */

__global__ void __launch_bounds__(128, 2)
tree_gemm_kernel(float* __restrict__ out,
                 const float* __restrict__ bb0, const float* __restrict__ bb1,
                 const float* __restrict__ bb2, const float* __restrict__ bb3,
                 const float* __restrict__ bb4, const float* __restrict__ bb5)
{
    extern __shared__ char smem[];
    const uint32_t sb = smem_u32(smem);
    const int tid  = threadIdx.x;
    const int lane = tid & 31;
    const int warp = tid >> 5;
    const int wm   = warp & 1;
    const int wn   = warp >> 1;

    const int bx = blockIdx.x;
    int lvl;
    if      (bx < 1)  lvl = 0;
    else if (bx < 2)  lvl = 1;
    else if (bx < 4)  lvl = 2;
    else if (bx < 11) lvl = 3;
    else if (bx < 35) lvl = 4;
    else              lvl = 5;
    const int    tstart[NLEV]  = {0, 1, 2, 4, 11, 35};
    const int    padbase[NLEV] = {0, 128, 256, 512, 1408, 4480};
    const int    Cs[NLEV]      = {20, 70, 250, 800, 3000, 12000};
    const size_t obase[NLEV]   = {0, (size_t)B_ROWS*20, (size_t)B_ROWS*90, (size_t)B_ROWS*340,
                                  (size_t)B_ROWS*1140, (size_t)B_ROWS*4140};
    const float* biasArr[NLEV] = {bb0, bb1, bb2, bb3, bb4, bb5};

    const int   n0l   = (bx - tstart[lvl]) * 128;
    const int   brow0 = padbase[lvl] + n0l;
    const int   C     = Cs[lvl];
    const size_t ob   = obase[lvl];
    const float* bias = biasArr[lvl];
    const int   m0    = blockIdx.y * 128;

    auto load_slab = [&](int ks, int st) {
        const int kofs = ks * 64;
        uint32_t base = sb + st * STAGE_BYTES;
#pragma unroll
        for (int i = 0; i < 8; i++) {
            int cid = tid + i * 128;
            int row = cid >> 3, c = cid & 7;
            uint32_t sw = row * 128 + ((c ^ (row & 7)) << 4);
            cp_async16(base + sw,
                       &g_A[(size_t)(m0 + row) * KDIM + kofs + c * 8]);
            cp_async16(base + B_OFF + sw,
                       &g_B[(size_t)(brow0 + row) * KDIM + kofs + c * 8]);
        }
    };

    // fragment loaders (per kk step within a K64 slab)
    auto ld_bfrag = [&](uint32_t base, int kk, uint32_t (&bf)[4][4]) {
#pragma unroll
        for (int nj4 = 0; nj4 < 4; nj4++) {
            int row = wn * 64 + nj4 * 16 + (lane & 7) + ((lane & 16) ? 8 : 0);
            int c   = kk * 2 + ((lane >> 3) & 1);
            ldsm_x4(bf[nj4], base + B_OFF + row * 128 + ((c ^ (row & 7)) << 4));
        }
    };
    auto ld_afrag = [&](uint32_t base, int kk, uint32_t (&af)[4][4]) {
#pragma unroll
        for (int mi = 0; mi < 4; mi++) {
            int row = wm * 64 + mi * 16 + (lane & 15);
            int c   = kk * 2 + (lane >> 4);
            ldsm_x4(af[mi], base + row * 128 + ((c ^ (row & 7)) << 4));
        }
    };

    float acc[4][8][4];
#pragma unroll
    for (int i = 0; i < 4; i++)
#pragma unroll
        for (int j = 0; j < 8; j++)
#pragma unroll
            for (int k = 0; k < 4; k++) acc[i][j][k] = 0.f;

    auto do_mma = [&](uint32_t (&af)[4][4], uint32_t (&bf)[4][4]) {
#pragma unroll
        for (int mi = 0; mi < 4; mi++)
#pragma unroll
            for (int nj = 0; nj < 8; nj++)
                mma16816(acc[mi][nj], af[mi],
                         bf[nj >> 1][(nj & 1) * 2], bf[nj >> 1][(nj & 1) * 2 + 1]);
    };

    load_slab(0, 0); cp_async_commit();
    load_slab(1, 1); cp_async_commit();

    int st = 0;
    for (int ks = 0; ks < NKS; ks++) {
        cp_async_wait1();
        __syncthreads();

        if (ks + 2 < NKS) load_slab(ks + 2, (ks + 2) % NSTAGE);
        cp_async_commit();

        uint32_t base = sb + st * STAGE_BYTES;

        // software-pipelined fragment loads: kk+1 frags issued before kk MMAs
        uint32_t a0[4][4], b0[4][4], a1[4][4], b1[4][4];
        ld_bfrag(base, 0, b0); ld_afrag(base, 0, a0);
        ld_bfrag(base, 1, b1); ld_afrag(base, 1, a1);
        do_mma(a0, b0);
        ld_bfrag(base, 2, b0); ld_afrag(base, 2, a0);
        do_mma(a1, b1);
        ld_bfrag(base, 3, b1); ld_afrag(base, 3, a1);
        do_mma(a0, b0);
        do_mma(a1, b1);

        st++; if (st == NSTAGE) st = 0;
    }

    // ---- epilogue: write exp(logit + bias) ----
    const int ncol0 = n0l + wn * 64;
    if (ncol0 + 64 <= C) {
#pragma unroll
        for (int mi = 0; mi < 4; mi++) {
            int r0 = m0 + wm * 64 + mi * 16 + (lane >> 2);
#pragma unroll
            for (int nj = 0; nj < 8; nj++) {
                int n = ncol0 + nj * 8 + (lane & 3) * 2;
                float2 bv = *reinterpret_cast<const float2*>(bias + n);
                float2 v0 = make_float2(__expf(acc[mi][nj][0] + bv.x),
                                        __expf(acc[mi][nj][1] + bv.y));
                float2 v1 = make_float2(__expf(acc[mi][nj][2] + bv.x),
                                        __expf(acc[mi][nj][3] + bv.y));
                *reinterpret_cast<float2*>(out + ob + (size_t)r0 * C + n)       = v0;
                *reinterpret_cast<float2*>(out + ob + (size_t)(r0 + 8) * C + n) = v1;
            }
        }
    } else {
#pragma unroll
        for (int mi = 0; mi < 4; mi++) {
            int r0 = m0 + wm * 64 + mi * 16 + (lane >> 2);
#pragma unroll
            for (int nj = 0; nj < 8; nj++) {
                int n = ncol0 + nj * 8 + (lane & 3) * 2;
                if (n < C) {
                    out[ob + (size_t)r0 * C + n]       = __expf(acc[mi][nj][0] + bias[n]);
                    out[ob + (size_t)(r0 + 8) * C + n] = __expf(acc[mi][nj][2] + bias[n]);
                }
                if (n + 1 < C) {
                    out[ob + (size_t)r0 * C + n + 1]       = __expf(acc[mi][nj][1] + bias[n + 1]);
                    out[ob + (size_t)(r0 + 8) * C + n + 1] = __expf(acc[mi][nj][3] + bias[n + 1]);
                }
            }
        }
    }
}

// ================= fused small levels: root + L1 + L2 + L3 =================
__global__ void __launch_bounds__(128)
chain_small_kernel(float* __restrict__ out)
{
    __shared__ float sA[800];
    __shared__ float sB[800];
    __shared__ float sred;

    const int b   = blockIdx.x;
    const int tid = threadIdx.x;

    float* row0 = out + (size_t)b * 20;
    float e = 0.f;
    if (tid < 20) e = row0[tid];
    if (tid < 32) {
        float v = e;
#pragma unroll
        for (int o = 16; o > 0; o >>= 1)
            v += __shfl_down_sync(0xffffffffu, v, o);
        if (tid == 0) sred = v;
    }
    __syncthreads();
    if (tid < 20) {
        float p = __fdividef(e, sred);
        row0[tid] = p;
        sA[tid]   = p;
    }
    __syncthreads();

    const int    Ps[3]  = {20, 70, 250};
    const int    Cs[3]  = {70, 250, 800};
    const int    Bo[3]  = {0, 20, 90};
    const size_t obs[3] = {(size_t)B_ROWS*20, (size_t)B_ROWS*90, (size_t)B_ROWS*340};

    float* prev = sA;
    float* cur  = sB;
#pragma unroll
    for (int l = 0; l < 3; l++) {
        const int P = Ps[l], C = Cs[l], bo = Bo[l];
        float* rowL = out + obs[l] + (size_t)b * C;
        for (int pid = tid; pid < P; pid += 128) {
            int s0 = __ldg(&g_gs[bo + pid]);
            int e0 = __ldg(&g_ge[bo + pid]);
            if (s0 >= e0) continue;
            float s = 0.f;
            for (int c = s0; c < e0; c++) s += __ldg(rowL + c);
            float scale = __fdividef(prev[pid], s);
            for (int c = s0; c < e0; c++) {
                float v = rowL[c] * scale;
                rowL[c] = v;
                cur[c]  = v;
            }
        }
        __syncthreads();
        float* t = prev; prev = cur; cur = t;
    }
}

// ================= seg softmax for big levels (values pre-exp'd) ==========
__global__ void seg_softmax_kernel(float* __restrict__ outL, const float* __restrict__ outP,
                                   int boff, int C, int P) {
    int idx = blockIdx.x * blockDim.x + threadIdx.x;
    if (idx >= B_ROWS * P) return;
    int b = idx / P;
    int pid = idx - b * P;
    int start = __ldg(&g_gs[boff + pid]);
    int end   = __ldg(&g_ge[boff + pid]);
    int len = end - start;
    if (len <= 0) return;

    float* row = outL + (size_t)b * C;
    float pp = __ldg(outP + (size_t)b * P + pid);

    if (len <= 8) {
        float ebuf[8];
        float s = 0.f;
#pragma unroll
        for (int i = 0; i < 8; i++) {
            float v = (i < len) ? __ldg(row + start + i) : 0.f;
            ebuf[i] = v;
            s += v;
        }
        float scale = __fdividef(pp, s);
#pragma unroll
        for (int i = 0; i < 8; i++)
            if (i < len) row[start + i] = ebuf[i] * scale;
    } else {
        float s = 0.f;
        for (int c = start; c < end; c++) s += __ldg(row + c);
        float scale = __fdividef(pp, s);
        for (int c = start; c < end; c++) row[c] = row[c] * scale;
    }
}

// ================= launch =================
extern "C" void kernel_launch(void* const* d_in, const int* in_sizes, int n_in,
                              void* d_out, int out_size)
{
    const float* x = (const float*)d_in[0];
    const float* W[NLEV];
    const float* bias[NLEV];
    for (int i = 0; i < NLEV; i++) {
        W[i]    = (const float*)d_in[1 + 2 * i];
        bias[i] = (const float*)d_in[2 + 2 * i];
    }
    const int* par[5];
    for (int l = 0; l < 5; l++) par[l] = (const int*)d_in[13 + l];
    float* out = (float*)d_out;

    cudaFuncSetAttribute(tree_gemm_kernel,
                         cudaFuncAttributeMaxDynamicSharedMemorySize, SMEM_TOTAL);

    // 1) fused prep: conv_x + conv_w + bounds
    prep_kernel<<<PREP_BLOCKS, 256>>>(x, W[0], W[1], W[2], W[3], W[4], W[5],
                                      par[0], par[1], par[2], par[3], par[4]);

    // 2) fused HMMA GEMM, writes exp(logit)
    dim3 grid(NTILES, MTILES);
    tree_gemm_kernel<<<grid, 128, SMEM_TOTAL>>>(out, bias[0], bias[1], bias[2],
                                                bias[3], bias[4], bias[5]);

    // 3) root + levels 1-3 fused (one block per row)
    chain_small_kernel<<<B_ROWS, 128>>>(out);

    // 4) level 4 (profiled slot)
    {
        int nthreads = B_ROWS * 800;
        seg_softmax_kernel<<<(nthreads + 255) / 256, 256>>>(
            out + (size_t)B_ROWS * 1140, out + (size_t)B_ROWS * 340, 340, 3000, 800);
    }
    // 5) level 5
    {
        int nthreads = B_ROWS * 3000;
        seg_softmax_kernel<<<(nthreads + 255) / 256, 256>>>(
            out + (size_t)B_ROWS * 4140, out + (size_t)B_ROWS * 1140, 1140, 12000, 3000);
    }
}